// round 2
// baseline (speedup 1.0000x reference)
#include <cuda_runtime.h>
#include <mma.h>
#include <math.h>

using namespace nvcuda;

#define NN 50000
#define EE 1600000
#define CC 50000
#define HH 512

// ---------------- scratch (static device globals; no allocation) ----------------
__device__ float g_h  [(size_t)NN * HH];
__device__ float g_mid[(size_t)NN * HH];
__device__ float g_xb [(size_t)NN * HH];
__device__ float g_act[(size_t)CC * HH];
__device__ float g_const[HH];
__device__ int   g_off[NN + 1];
__device__ int   g_cur[NN];
__device__ int   g_csr[EE];

// ---------------- CSR build ----------------
__global__ void k_zero_off(int n) {
    int i = blockIdx.x * blockDim.x + threadIdx.x;
    if (i <= n) g_off[i] = 0;
}

__global__ void k_hist(const int* __restrict__ ei, int E) {
    int e = blockIdx.x * blockDim.x + threadIdx.x;
    if (e < E) {
        int dst = ei[E + e];
        atomicAdd(&g_off[dst + 1], 1);
    }
}

__global__ void k_scan(int n) {  // inclusive scan of g_off[1..n], single block 1024
    __shared__ int s[1024];
    __shared__ int carry;
    int tid = threadIdx.x;
    if (tid == 0) carry = 0;
    __syncthreads();
    for (int base = 1; base <= n; base += 1024) {
        int i = base + tid;
        int v = (i <= n) ? g_off[i] : 0;
        s[tid] = v;
        __syncthreads();
        for (int d = 1; d < 1024; d <<= 1) {
            int tv = (tid >= d) ? s[tid - d] : 0;
            __syncthreads();
            s[tid] += tv;
            __syncthreads();
        }
        int res = carry + s[tid];
        if (i <= n) g_off[i] = res;
        __syncthreads();
        if (tid == 1023) carry = res;
        __syncthreads();
    }
}

__global__ void k_initcur(int n) {
    int i = blockIdx.x * blockDim.x + threadIdx.x;
    if (i < n) g_cur[i] = g_off[i];
}

__global__ void k_scatter(const int* __restrict__ ei, int E) {
    int e = blockIdx.x * blockDim.x + threadIdx.x;
    if (e < E) {
        int src = ei[e];
        int dst = ei[E + e];
        int p = atomicAdd(&g_cur[dst], 1);
        g_csr[p] = src;
    }
}

// ---------------- aggregation: h[i] = x[i] + sum_{j->i} x[j] ----------------
template <int D4>  // D4 = feature_dim/4
__global__ void k_agg(const float* __restrict__ xin, float* __restrict__ hout, int nnodes) {
    constexpr int NPB = 128 / D4;
    int node = blockIdx.x * NPB + threadIdx.x / D4;
    int col  = threadIdx.x % D4;
    if (node >= nnodes) return;
    const float4* x4 = (const float4*)xin;
    float4 acc = x4[(size_t)node * D4 + col];
    int s = g_off[node], e = g_off[node + 1];
    for (int j = s; j < e; j++) {
        int nb = g_csr[j];
        float4 v = x4[(size_t)nb * D4 + col];
        acc.x += v.x; acc.y += v.y; acc.z += v.z; acc.w += v.w;
    }
    ((float4*)hout)[(size_t)node * D4 + col] = acc;
}

// ---------------- 3xTF32 GEMM: C = op(A @ B + bias) ----------------
// A[M,K] row-major (or gathered candidate features if cand != nullptr),
// B[K,N] row-major, bias[N]. BM=128, BN=128, BK=16, 256 threads, 8 warps (2x4),
// each warp: 64x32 = 4x2 frags of 16x16, m16n16k8 tf32 with hi/lo split.
__global__ __launch_bounds__(256) void k_gemm(
    const float* __restrict__ A, const float* __restrict__ B,
    const float* __restrict__ bias, float* __restrict__ C,
    int M, int N, int K, int relu,
    const int* __restrict__ cand, const float* __restrict__ xsrc)
{
    __shared__ float sm[4096];
    float* As = sm;          // 128 x 16
    float* Bs = sm + 2048;   // 16 x 128

    int tid  = threadIdx.x;
    int warp = tid >> 5, lane = tid & 31;
    int row0 = blockIdx.y * 128;
    int col0 = blockIdx.x * 128;
    int wm = warp >> 2, wn = warp & 3;

    typedef wmma::fragment<wmma::matrix_a, 16, 16, 8, wmma::precision::tf32, wmma::row_major> FragA;
    typedef wmma::fragment<wmma::matrix_b, 16, 16, 8, wmma::precision::tf32, wmma::row_major> FragB;
    typedef wmma::fragment<wmma::accumulator, 16, 16, 8, float> FragC;

    FragC acc[4][2];
    #pragma unroll
    for (int i = 0; i < 4; i++)
        #pragma unroll
        for (int j = 0; j < 2; j++)
            wmma::fill_fragment(acc[i][j], 0.0f);

    int arow = tid >> 1, aseg = tid & 1;     // A tile: 128 rows x (2 x 8 floats)
    int brow = tid >> 4, bseg = tid & 15;    // B tile: 16 rows x (16 x 8 floats)

    for (int k0 = 0; k0 < K; k0 += 16) {
        // ---- load A tile ----
        {
            int gr = row0 + arow;
            int kbase = k0 + aseg * 8;
            float4 v0 = make_float4(0.f, 0.f, 0.f, 0.f);
            float4 v1 = v0;
            if (gr < M) {
                if (cand) {
                    int u = cand[2 * gr], v = cand[2 * gr + 1];
                    const float4* xu4 = (const float4*)(xsrc + (size_t)u * HH);
                    const float4* xv4 = (const float4*)(xsrc + (size_t)v * HH);
                    if (kbase < HH) {
                        int q = kbase >> 2;
                        float4 a0 = xu4[q],     b0 = xv4[q];
                        float4 a1 = xu4[q + 1], b1 = xv4[q + 1];
                        v0 = make_float4(a0.x + b0.x, a0.y + b0.y, a0.z + b0.z, a0.w + b0.w);
                        v1 = make_float4(a1.x + b1.x, a1.y + b1.y, a1.z + b1.z, a1.w + b1.w);
                    } else {
                        int q = (kbase - HH) >> 2;
                        float4 a0 = xu4[q],     b0 = xv4[q];
                        float4 a1 = xu4[q + 1], b1 = xv4[q + 1];
                        v0 = make_float4(fabsf(a0.x - b0.x), fabsf(a0.y - b0.y),
                                         fabsf(a0.z - b0.z), fabsf(a0.w - b0.w));
                        v1 = make_float4(fabsf(a1.x - b1.x), fabsf(a1.y - b1.y),
                                         fabsf(a1.z - b1.z), fabsf(a1.w - b1.w));
                    }
                } else {
                    const float4* Ap = (const float4*)(A + (size_t)gr * K + kbase);
                    v0 = Ap[0]; v1 = Ap[1];
                }
            }
            float* dst = As + arow * 16 + aseg * 8;
            ((float4*)dst)[0] = v0;
            ((float4*)dst)[1] = v1;
        }
        // ---- load B tile ----
        {
            const float4* Bp = (const float4*)(B + (size_t)(k0 + brow) * N + col0 + bseg * 8);
            float4 b0 = Bp[0], b1 = Bp[1];
            float* dst = Bs + brow * 128 + bseg * 8;
            ((float4*)dst)[0] = b0;
            ((float4*)dst)[1] = b1;
        }
        __syncthreads();

        #pragma unroll
        for (int kk = 0; kk < 16; kk += 8) {
            FragB braw, bhi[2], blo[2];
            #pragma unroll
            for (int j = 0; j < 2; j++) {
                wmma::load_matrix_sync(braw, Bs + kk * 128 + wn * 32 + j * 16, 128);
                #pragma unroll
                for (int e = 0; e < braw.num_elements; e++) {
                    float hv = wmma::__float_to_tf32(braw.x[e]);
                    bhi[j].x[e] = hv;
                    blo[j].x[e] = wmma::__float_to_tf32(braw.x[e] - hv);
                }
            }
            #pragma unroll
            for (int i = 0; i < 4; i++) {
                FragA araw, ahi, alo;
                wmma::load_matrix_sync(araw, As + (wm * 64 + i * 16) * 16 + kk, 16);
                #pragma unroll
                for (int e = 0; e < araw.num_elements; e++) {
                    float hv = wmma::__float_to_tf32(araw.x[e]);
                    ahi.x[e] = hv;
                    alo.x[e] = wmma::__float_to_tf32(araw.x[e] - hv);
                }
                #pragma unroll
                for (int j = 0; j < 2; j++) {
                    wmma::mma_sync(acc[i][j], ahi, bhi[j], acc[i][j]);
                    wmma::mma_sync(acc[i][j], ahi, blo[j], acc[i][j]);
                    wmma::mma_sync(acc[i][j], alo, bhi[j], acc[i][j]);
                }
            }
        }
        __syncthreads();
    }

    // ---- epilogue: staged store with bias + relu + bounds guard ----
    float* stage = sm + warp * 320;  // 16 x 20 per warp (reuses As/Bs)
    int lr = lane >> 1, lc0 = (lane & 1) * 8;
    #pragma unroll
    for (int i = 0; i < 4; i++) {
        #pragma unroll
        for (int j = 0; j < 2; j++) {
            wmma::store_matrix_sync(stage, acc[i][j], 20, wmma::mem_row_major);
            __syncwarp();
            int gr  = row0 + wm * 64 + i * 16 + lr;
            int gcb = col0 + wn * 32 + j * 16 + lc0;
            if (gr < M) {
                #pragma unroll
                for (int c = 0; c < 8; c++) {
                    int gc = gcb + c;
                    float val = stage[lr * 20 + lc0 + c] + bias[gc];
                    if (relu) val = fmaxf(val, 0.0f);
                    C[(size_t)gr * N + gc] = val;
                }
            }
            __syncwarp();
        }
    }
}

// ---------------- head: t_embed, first_feat, const_vec ----------------
__global__ void k_head(const float* __restrict__ xfin, const int* __restrict__ fe,
                       const float* __restrict__ t,
                       const float* __restrict__ tw1, const float* __restrict__ tb1,
                       const float* __restrict__ tw2, const float* __restrict__ tb2,
                       const float* __restrict__ pw1, const float* __restrict__ pb1)
{
    __shared__ float s_hid[HH];
    __shared__ float s_f[2 * HH];
    __shared__ float s_te[HH];
    int tid = threadIdx.x;  // 512 threads
    float tv = t[0];
    s_hid[tid] = fmaxf(tv * tw1[tid] + tb1[tid], 0.0f);
    int u = fe[0], v = fe[1];
    float xu = xfin[(size_t)u * HH + tid];
    float xv = xfin[(size_t)v * HH + tid];
    s_f[tid]      = xu + xv;
    s_f[HH + tid] = fabsf(xu - xv);
    __syncthreads();
    float te = tb2[tid];
    for (int j = 0; j < HH; j++) te += s_hid[j] * tw2[(size_t)j * HH + tid];
    s_te[tid] = te;
    __syncthreads();
    float cv = pb1[tid];
    for (int i = 0; i < 2 * HH; i++) cv += s_f[i] * pw1[(size_t)i * HH + tid];
    for (int i = 0; i < HH; i++)     cv += s_te[i] * pw1[(size_t)(2 * HH + i) * HH + tid];
    g_const[tid] = cv;
}

// ---------------- final: logits[c] = relu_act[c] . pred_w2 + pred_b2 ----------------
__global__ void k_logits(const float* __restrict__ act, const float* __restrict__ w2,
                         const float* __restrict__ b2, float* __restrict__ out, int C)
{
    __shared__ float sw[HH];
    int tid = threadIdx.x;
    for (int i = tid; i < HH; i += 256) sw[i] = w2[i];
    __syncthreads();
    int r = blockIdx.x * 8 + (tid >> 5);
    int lane = tid & 31;
    if (r >= C) return;
    float sum = 0.0f;
    const float* row = act + (size_t)r * HH;
    for (int k = lane; k < HH; k += 32) sum += row[k] * sw[k];
    #pragma unroll
    for (int o = 16; o > 0; o >>= 1) sum += __shfl_down_sync(0xFFFFFFFFu, sum, o);
    if (lane == 0) out[r] = sum + b2[0];
}

// ---------------- launch ----------------
extern "C" void kernel_launch(void* const* d_in, const int* in_sizes, int n_in,
                              void* d_out, int out_size)
{
    const float* x    = (const float*)d_in[0];
    const int*   ei   = (const int*)  d_in[1];
    const int*   fe   = (const int*)  d_in[2];
    const int*   cand = (const int*)  d_in[3];
    const float* t    = (const float*)d_in[4];
    const float* gw1[3] = {(const float*)d_in[5],  (const float*)d_in[9],  (const float*)d_in[13]};
    const float* gb1[3] = {(const float*)d_in[6],  (const float*)d_in[10], (const float*)d_in[14]};
    const float* gw2[3] = {(const float*)d_in[7],  (const float*)d_in[11], (const float*)d_in[15]};
    const float* gb2[3] = {(const float*)d_in[8],  (const float*)d_in[12], (const float*)d_in[16]};
    const float* pw1 = (const float*)d_in[17];
    const float* pb1 = (const float*)d_in[18];
    const float* pw2 = (const float*)d_in[19];
    const float* pb2 = (const float*)d_in[20];
    const float* tw1 = (const float*)d_in[21];
    const float* tb1 = (const float*)d_in[22];
    const float* tw2 = (const float*)d_in[23];
    const float* tb2 = (const float*)d_in[24];

    int Nn = in_sizes[0] / 128;
    int E  = in_sizes[1] / 2;
    int Cc = in_sizes[3] / 2;

    float *p_h, *p_mid, *p_x, *p_act, *p_const;
    cudaGetSymbolAddress((void**)&p_h,     g_h);
    cudaGetSymbolAddress((void**)&p_mid,   g_mid);
    cudaGetSymbolAddress((void**)&p_x,     g_xb);
    cudaGetSymbolAddress((void**)&p_act,   g_act);
    cudaGetSymbolAddress((void**)&p_const, g_const);

    // CSR build (recomputed every call — deterministic work)
    k_zero_off<<<(Nn + 1 + 255) / 256, 256>>>(Nn);
    k_hist<<<(E + 255) / 256, 256>>>(ei, E);
    k_scan<<<1, 1024>>>(Nn);
    k_initcur<<<(Nn + 255) / 256, 256>>>(Nn);
    k_scatter<<<(E + 255) / 256, 256>>>(ei, E);

    dim3 gB(4, (Nn + 127) / 128);   // N=512 -> 4 col blocks

    // layer 0 (D=128 -> 512)
    k_agg<32><<<(Nn + 3) / 4, 128>>>(x, p_h, Nn);
    k_gemm<<<gB, 256>>>(p_h,   gw1[0], gb1[0], p_mid, Nn, 512, 128, 1, nullptr, nullptr);
    k_gemm<<<gB, 256>>>(p_mid, gw2[0], gb2[0], p_x,   Nn, 512, 512, 0, nullptr, nullptr);
    // layers 1, 2 (512 -> 512)
    for (int l = 1; l < 3; l++) {
        k_agg<128><<<Nn, 128>>>(p_x, p_h, Nn);
        k_gemm<<<gB, 256>>>(p_h,   gw1[l], gb1[l], p_mid, Nn, 512, 512, 1, nullptr, nullptr);
        k_gemm<<<gB, 256>>>(p_mid, gw2[l], gb2[l], p_x,   Nn, 512, 512, 0, nullptr, nullptr);
    }

    // head: t_embed + first_feat + fold into const vector
    k_head<<<1, 512>>>(p_x, fe, t, tw1, tb1, tw2, tb2, pw1, pb1);

    // candidate GEMM: A rows gathered as [xu+xv, |xu-xv|], W_cand = pred_w1 rows [1024:2048)
    dim3 gC(4, (Cc + 127) / 128);
    k_gemm<<<gC, 256>>>(nullptr, pw1 + (size_t)2 * HH * HH, p_const, p_act,
                        Cc, 512, 1024, 1, cand, p_x);

    // final dot with pred_w2
    k_logits<<<(Cc + 7) / 8, 256>>>(p_act, pw2, pb2, (float*)d_out, Cc);
}

// round 3
// speedup vs baseline: 2.4714x; 2.4714x over previous
#include <cuda_runtime.h>
#include <cuda_bf16.h>
#include <mma.h>
#include <math.h>

using namespace nvcuda;

#define NN 50000
#define EE 1600000
#define CC 50000
#define HH 512

// ---------------- scratch (static device globals; no allocation) ----------------
__device__ float g_h  [(size_t)NN * HH];
__device__ float g_mid[(size_t)NN * HH];
__device__ float g_xb [(size_t)NN * HH];
__device__ float g_act[(size_t)CC * HH];
__device__ float g_const[HH];
__device__ int   g_off[NN + 1];
__device__ int   g_cur[NN];
__device__ int   g_csr[EE];

// bf16 hi/lo planes for all weights (concatenated)
// w0a:128x512 @0, w0b:512x512 @65536, w1a @327680, w1b @589824,
// w2a @851968, w2b @1114112, wcand:1024x512 @1376256  -> total 1900544
#define WTOT 1900544
__device__ __nv_bfloat16 g_wh[WTOT];
__device__ __nv_bfloat16 g_wl[WTOT];

// ---------------- weight conversion: fp32 -> bf16 hi/lo planes ----------------
__global__ void k_wconv(const float* __restrict__ s0, const float* __restrict__ s1,
                        const float* __restrict__ s2, const float* __restrict__ s3,
                        const float* __restrict__ s4, const float* __restrict__ s5,
                        const float* __restrict__ s6)
{
    const float* srcs[7] = {s0, s1, s2, s3, s4, s5, s6};
    const int sizes[7] = {65536, 262144, 262144, 262144, 262144, 262144, 524288};
    const int offs[7]  = {0, 65536, 327680, 589824, 851968, 1114112, 1376256};
    int seg = blockIdx.y;
    const float* s = srcs[seg];
    int off = offs[seg], sz = sizes[seg];
    for (int i = blockIdx.x * blockDim.x + threadIdx.x; i < sz; i += gridDim.x * blockDim.x) {
        float v = s[i];
        __nv_bfloat16 hi = __float2bfloat16_rn(v);
        g_wh[off + i] = hi;
        g_wl[off + i] = __float2bfloat16_rn(v - __bfloat162float(hi));
    }
}

// ---------------- CSR build ----------------
__global__ void k_hist(const int* __restrict__ ei, int E) {
    int e = blockIdx.x * blockDim.x + threadIdx.x;
    if (e < E) {
        int dst = ei[E + e];
        atomicAdd(&g_off[dst + 1], 1);
    }
}

__global__ void k_scan(int n) {  // inclusive scan of g_off[1..n] + init g_cur
    __shared__ int s[1024];
    __shared__ int carry;
    int tid = threadIdx.x;
    if (tid == 0) { carry = 0; g_cur[0] = 0; }
    __syncthreads();
    for (int base = 1; base <= n; base += 1024) {
        int i = base + tid;
        int v = (i <= n) ? g_off[i] : 0;
        s[tid] = v;
        __syncthreads();
        for (int d = 1; d < 1024; d <<= 1) {
            int tv = (tid >= d) ? s[tid - d] : 0;
            __syncthreads();
            s[tid] += tv;
            __syncthreads();
        }
        int res = carry + s[tid];
        if (i <= n) {
            g_off[i] = res;
            if (i < n) g_cur[i] = res;
        }
        __syncthreads();
        if (tid == 1023) carry = res;
        __syncthreads();
    }
}

__global__ void k_scatter(const int* __restrict__ ei, int E) {
    int e = blockIdx.x * blockDim.x + threadIdx.x;
    if (e < E) {
        int src = ei[e];
        int dst = ei[E + e];
        int p = atomicAdd(&g_cur[dst], 1);
        g_csr[p] = src;
    }
}

// ---------------- aggregation: h[i] = x[i] + sum_{j->i} x[j] ----------------
template <int D4>  // D4 = feature_dim/4
__global__ void k_agg(const float* __restrict__ xin, float* __restrict__ hout, int nnodes) {
    constexpr int NPB = 128 / D4;
    int node = blockIdx.x * NPB + threadIdx.x / D4;
    int col  = threadIdx.x % D4;
    if (node >= nnodes) return;
    const float4* x4 = (const float4*)xin;
    float4 acc = x4[(size_t)node * D4 + col];
    int s = g_off[node], e = g_off[node + 1];
    for (int j = s; j < e; j++) {
        int nb = g_csr[j];
        float4 v = x4[(size_t)nb * D4 + col];
        acc.x += v.x; acc.y += v.y; acc.z += v.z; acc.w += v.w;
    }
    ((float4*)hout)[(size_t)node * D4 + col] = acc;
}

// ---------------- split-bf16 GEMM: C = op(A @ B + bias) ----------------
// A[M,K] fp32 row-major (or gathered candidate features if cand != nullptr),
// B given as precomputed bf16 hi/lo planes [K,N] row-major, bias[N].
// BM=128, BN=128, BK=16, 256 threads, 8 warps (2x4),
// each warp 64x32 = 4x2 frags of 16x16, mma m16n16k16 bf16, 3-term split:
// C ~= Ah*Bh + Ah*Bl + Al*Bh   (effective ~16-bit mantissa)
#define A_LD 24     // 16 + 8 pad  (row stride 48B, 16B-aligned)
#define B_LD 144    // 128 + 16 pad (row stride 288B, 16B-aligned)
__global__ __launch_bounds__(256) void k_gemm(
    const float* __restrict__ A,
    const __nv_bfloat16* __restrict__ Bh, const __nv_bfloat16* __restrict__ Bl,
    const float* __restrict__ bias, float* __restrict__ C,
    int M, int N, int K, int relu,
    const int* __restrict__ cand, const float* __restrict__ xsrc)
{
    __shared__ __nv_bfloat16 As_h[128 * A_LD];
    __shared__ __nv_bfloat16 As_l[128 * A_LD];
    __shared__ __nv_bfloat16 Bs_h[16 * B_LD];
    __shared__ __nv_bfloat16 Bs_l[16 * B_LD];
    __shared__ float stage_sm[8 * 320];

    int tid  = threadIdx.x;
    int warp = tid >> 5, lane = tid & 31;
    int row0 = blockIdx.y * 128;
    int col0 = blockIdx.x * 128;
    int wm = warp >> 2, wn = warp & 3;

    typedef wmma::fragment<wmma::matrix_a, 16, 16, 16, __nv_bfloat16, wmma::row_major> FragA;
    typedef wmma::fragment<wmma::matrix_b, 16, 16, 16, __nv_bfloat16, wmma::row_major> FragB;
    typedef wmma::fragment<wmma::accumulator, 16, 16, 16, float> FragC;

    FragC acc[4][2];
    #pragma unroll
    for (int i = 0; i < 4; i++)
        #pragma unroll
        for (int j = 0; j < 2; j++)
            wmma::fill_fragment(acc[i][j], 0.0f);

    int arow = tid >> 1, aseg = tid & 1;     // A tile: 128 rows x (2 x 8 floats)
    int brow = tid >> 4, bseg = tid & 15;    // B tile: 16 rows x (16 x 8 bf16)

    for (int k0 = 0; k0 < K; k0 += 16) {
        // ---- load + convert A tile (8 floats per thread -> bf16 hi/lo) ----
        {
            int gr = row0 + arow;
            int kbase = k0 + aseg * 8;
            float4 v0 = make_float4(0.f, 0.f, 0.f, 0.f);
            float4 v1 = v0;
            if (gr < M) {
                if (cand) {
                    int u = cand[2 * gr], v = cand[2 * gr + 1];
                    const float4* xu4 = (const float4*)(xsrc + (size_t)u * HH);
                    const float4* xv4 = (const float4*)(xsrc + (size_t)v * HH);
                    if (kbase < HH) {
                        int q = kbase >> 2;
                        float4 a0 = xu4[q],     b0 = xv4[q];
                        float4 a1 = xu4[q + 1], b1 = xv4[q + 1];
                        v0 = make_float4(a0.x + b0.x, a0.y + b0.y, a0.z + b0.z, a0.w + b0.w);
                        v1 = make_float4(a1.x + b1.x, a1.y + b1.y, a1.z + b1.z, a1.w + b1.w);
                    } else {
                        int q = (kbase - HH) >> 2;
                        float4 a0 = xu4[q],     b0 = xv4[q];
                        float4 a1 = xu4[q + 1], b1 = xv4[q + 1];
                        v0 = make_float4(fabsf(a0.x - b0.x), fabsf(a0.y - b0.y),
                                         fabsf(a0.z - b0.z), fabsf(a0.w - b0.w));
                        v1 = make_float4(fabsf(a1.x - b1.x), fabsf(a1.y - b1.y),
                                         fabsf(a1.z - b1.z), fabsf(a1.w - b1.w));
                    }
                } else {
                    const float4* Ap = (const float4*)(A + (size_t)gr * K + kbase);
                    v0 = Ap[0]; v1 = Ap[1];
                }
            }
            float vals[8] = {v0.x, v0.y, v0.z, v0.w, v1.x, v1.y, v1.z, v1.w};
            __nv_bfloat16 hi[8], lo[8];
            #pragma unroll
            for (int c = 0; c < 8; c++) {
                hi[c] = __float2bfloat16_rn(vals[c]);
                lo[c] = __float2bfloat16_rn(vals[c] - __bfloat162float(hi[c]));
            }
            int so = arow * A_LD + aseg * 8;
            *(uint4*)(As_h + so) = *(uint4*)hi;
            *(uint4*)(As_l + so) = *(uint4*)lo;
        }
        // ---- load B tile (precomputed bf16 hi/lo) ----
        {
            size_t go = (size_t)(k0 + brow) * N + col0 + bseg * 8;
            int so = brow * B_LD + bseg * 8;
            *(uint4*)(Bs_h + so) = *(const uint4*)(Bh + go);
            *(uint4*)(Bs_l + so) = *(const uint4*)(Bl + go);
        }
        __syncthreads();

        // ---- mma: one K=16 step per tile ----
        {
            FragB bh[2], bl[2];
            #pragma unroll
            for (int j = 0; j < 2; j++) {
                wmma::load_matrix_sync(bh[j], Bs_h + wn * 32 + j * 16, B_LD);
                wmma::load_matrix_sync(bl[j], Bs_l + wn * 32 + j * 16, B_LD);
            }
            #pragma unroll
            for (int i = 0; i < 4; i++) {
                FragA ah, al;
                wmma::load_matrix_sync(ah, As_h + (wm * 64 + i * 16) * A_LD, A_LD);
                wmma::load_matrix_sync(al, As_l + (wm * 64 + i * 16) * A_LD, A_LD);
                #pragma unroll
                for (int j = 0; j < 2; j++) {
                    wmma::mma_sync(acc[i][j], ah, bh[j], acc[i][j]);
                    wmma::mma_sync(acc[i][j], ah, bl[j], acc[i][j]);
                    wmma::mma_sync(acc[i][j], al, bh[j], acc[i][j]);
                }
            }
        }
        __syncthreads();
    }

    // ---- epilogue: staged store with bias + relu + bounds guard ----
    float* stage = stage_sm + warp * 320;  // 16 x 20 per warp
    int lr = lane >> 1, lc0 = (lane & 1) * 8;
    #pragma unroll
    for (int i = 0; i < 4; i++) {
        #pragma unroll
        for (int j = 0; j < 2; j++) {
            wmma::store_matrix_sync(stage, acc[i][j], 20, wmma::mem_row_major);
            __syncwarp();
            int gr  = row0 + wm * 64 + i * 16 + lr;
            int gcb = col0 + wn * 32 + j * 16 + lc0;
            if (gr < M) {
                #pragma unroll
                for (int c = 0; c < 8; c++) {
                    int gc = gcb + c;
                    float val = stage[lr * 20 + lc0 + c] + bias[gc];
                    if (relu) val = fmaxf(val, 0.0f);
                    C[(size_t)gr * N + gc] = val;
                }
            }
            __syncwarp();
        }
    }
}

// ---------------- head: t_embed, first_feat, const_vec ----------------
__global__ void k_head(const float* __restrict__ xfin, const int* __restrict__ fe,
                       const float* __restrict__ t,
                       const float* __restrict__ tw1, const float* __restrict__ tb1,
                       const float* __restrict__ tw2, const float* __restrict__ tb2,
                       const float* __restrict__ pw1, const float* __restrict__ pb1)
{
    __shared__ float s_hid[HH];
    __shared__ float s_f[2 * HH];
    __shared__ float s_te[HH];
    int tid = threadIdx.x;  // 512 threads
    float tv = t[0];
    s_hid[tid] = fmaxf(tv * tw1[tid] + tb1[tid], 0.0f);
    int u = fe[0], v = fe[1];
    float xu = xfin[(size_t)u * HH + tid];
    float xv = xfin[(size_t)v * HH + tid];
    s_f[tid]      = xu + xv;
    s_f[HH + tid] = fabsf(xu - xv);
    __syncthreads();
    float te = tb2[tid];
    for (int j = 0; j < HH; j++) te += s_hid[j] * tw2[(size_t)j * HH + tid];
    s_te[tid] = te;
    __syncthreads();
    float cv = pb1[tid];
    for (int i = 0; i < 2 * HH; i++) cv += s_f[i] * pw1[(size_t)i * HH + tid];
    for (int i = 0; i < HH; i++)     cv += s_te[i] * pw1[(size_t)(2 * HH + i) * HH + tid];
    g_const[tid] = cv;
}

// ---------------- final: logits[c] = relu_act[c] . pred_w2 + pred_b2 ----------------
__global__ void k_logits(const float* __restrict__ act, const float* __restrict__ w2,
                         const float* __restrict__ b2, float* __restrict__ out, int C)
{
    __shared__ float sw[HH];
    int tid = threadIdx.x;
    for (int i = tid; i < HH; i += 256) sw[i] = w2[i];
    __syncthreads();
    int r = blockIdx.x * 8 + (tid >> 5);
    int lane = tid & 31;
    if (r >= C) return;
    float sum = 0.0f;
    const float* row = act + (size_t)r * HH;
    for (int k = lane; k < HH; k += 32) sum += row[k] * sw[k];
    #pragma unroll
    for (int o = 16; o > 0; o >>= 1) sum += __shfl_down_sync(0xFFFFFFFFu, sum, o);
    if (lane == 0) out[r] = sum + b2[0];
}

// ---------------- launch ----------------
extern "C" void kernel_launch(void* const* d_in, const int* in_sizes, int n_in,
                              void* d_out, int out_size)
{
    const float* x    = (const float*)d_in[0];
    const int*   ei   = (const int*)  d_in[1];
    const int*   fe   = (const int*)  d_in[2];
    const int*   cand = (const int*)  d_in[3];
    const float* t    = (const float*)d_in[4];
    const float* gw1[3] = {(const float*)d_in[5],  (const float*)d_in[9],  (const float*)d_in[13]};
    const float* gb1[3] = {(const float*)d_in[6],  (const float*)d_in[10], (const float*)d_in[14]};
    const float* gw2[3] = {(const float*)d_in[7],  (const float*)d_in[11], (const float*)d_in[15]};
    const float* gb2[3] = {(const float*)d_in[8],  (const float*)d_in[12], (const float*)d_in[16]};
    const float* pw1 = (const float*)d_in[17];
    const float* pb1 = (const float*)d_in[18];
    const float* pw2 = (const float*)d_in[19];
    const float* pb2 = (const float*)d_in[20];
    const float* tw1 = (const float*)d_in[21];
    const float* tb1 = (const float*)d_in[22];
    const float* tw2 = (const float*)d_in[23];
    const float* tb2 = (const float*)d_in[24];

    int Nn = in_sizes[0] / 128;
    int E  = in_sizes[1] / 2;
    int Cc = in_sizes[3] / 2;

    float *p_h, *p_mid, *p_x, *p_act, *p_const;
    int *p_off;
    __nv_bfloat16 *p_wh, *p_wl;
    cudaGetSymbolAddress((void**)&p_h,     g_h);
    cudaGetSymbolAddress((void**)&p_mid,   g_mid);
    cudaGetSymbolAddress((void**)&p_x,     g_xb);
    cudaGetSymbolAddress((void**)&p_act,   g_act);
    cudaGetSymbolAddress((void**)&p_const, g_const);
    cudaGetSymbolAddress((void**)&p_off,   g_off);
    cudaGetSymbolAddress((void**)&p_wh,    g_wh);
    cudaGetSymbolAddress((void**)&p_wl,    g_wl);

    const size_t OFF_W[7] = {0, 65536, 327680, 589824, 851968, 1114112, 1376256};

    // weight conversion (one launch)
    k_wconv<<<dim3(64, 7), 256>>>(gw1[0], gw2[0], gw1[1], gw2[1], gw1[2], gw2[2],
                                  pw1 + (size_t)2 * HH * HH);

    // CSR build (recomputed every call — deterministic work)
    cudaMemsetAsync(p_off, 0, (size_t)(Nn + 1) * sizeof(int));
    k_hist<<<(E + 255) / 256, 256>>>(ei, E);
    k_scan<<<1, 1024>>>(Nn);
    k_scatter<<<(E + 255) / 256, 256>>>(ei, E);

    dim3 gB(4, (Nn + 127) / 128);   // N=512 -> 4 col blocks

    // layer 0 (D=128 -> 512)
    k_agg<32><<<(Nn + 3) / 4, 128>>>(x, p_h, Nn);
    k_gemm<<<gB, 256>>>(p_h,   p_wh + OFF_W[0], p_wl + OFF_W[0], gb1[0], p_mid,
                        Nn, 512, 128, 1, nullptr, nullptr);
    k_gemm<<<gB, 256>>>(p_mid, p_wh + OFF_W[1], p_wl + OFF_W[1], gb2[0], p_x,
                        Nn, 512, 512, 0, nullptr, nullptr);
    // layers 1, 2 (512 -> 512)
    for (int l = 1; l < 3; l++) {
        k_agg<128><<<Nn, 128>>>(p_x, p_h, Nn);
        k_gemm<<<gB, 256>>>(p_h,   p_wh + OFF_W[2 * l], p_wl + OFF_W[2 * l], gb1[l], p_mid,
                            Nn, 512, 512, 1, nullptr, nullptr);
        k_gemm<<<gB, 256>>>(p_mid, p_wh + OFF_W[2 * l + 1], p_wl + OFF_W[2 * l + 1], gb2[l], p_x,
                            Nn, 512, 512, 0, nullptr, nullptr);
    }

    // head: t_embed + first_feat + fold into const vector
    k_head<<<1, 512>>>(p_x, fe, t, tw1, tb1, tw2, tb2, pw1, pb1);

    // candidate GEMM: A rows gathered as [xu+xv, |xu-xv|], W = pred_w1 rows [1024:2048)
    dim3 gC(4, (Cc + 127) / 128);
    k_gemm<<<gC, 256>>>(nullptr, p_wh + OFF_W[6], p_wl + OFF_W[6], p_const, p_act,
                        Cc, 512, 1024, 1, cand, p_x);

    // final dot with pred_w2
    k_logits<<<(Cc + 7) / 8, 256>>>(p_act, pw2, pb2, (float*)d_out, Cc);
}